// round 16
// baseline (speedup 1.0000x reference)
#include <cuda_runtime.h>
#include <cstdint>
#include <math.h>

// Q,K,V,O : [4,16,4096,64] fp32.
// out = rmsnorm( V * (1 + silu( rmsnorm(cumsum_s(silu(V)*V)) / (||Q||+||K||+1+2e-8) )) )
//
// R9 champion + r_row computed AT KERNEL ENTRY (before phase A): Q/K are
// streamed and reduced to the 64 per-row gate denominators immediately, so
// V+Q+K DRAM traffic all starts at cycle 0 and phase B has no global loads.
// No extra barriers (phase A's syncthreads orders r_row); no persistent regs.

#define BH      64
#define SEQ     4096
#define DIM     64
#define CHUNK   64
#define NCHUNK  64
#define NGRP    16
#define NBLK    (BH * NCHUNK)   // 4096

__device__ float g_agg[NBLK * DIM];   // [bh][ch][d]
__device__ int   g_flag[NBLK];        // [bh][ch]

__device__ __forceinline__ float sigf(float x) {
    return __fdividef(1.0f, 1.0f + __expf(-x));
}
__device__ __forceinline__ float4 add4(float4 a, float4 b) {
    return make_float4(a.x + b.x, a.y + b.y, a.z + b.z, a.w + b.w);
}
__device__ __forceinline__ float4 sw4(float4 v) {
    return make_float4(v.x * v.x * sigf(v.x), v.y * v.y * sigf(v.y),
                       v.z * v.z * sigf(v.z), v.w * v.w * sigf(v.w));
}
__device__ __forceinline__ float dot4(float4 a) {
    return a.x * a.x + a.y * a.y + a.z * a.z + a.w * a.w;
}
__device__ __forceinline__ int ld_acq(const int* p) {
    int v;
    asm volatile("ld.global.acquire.gpu.b32 %0, [%1];" : "=r"(v) : "l"(p) : "memory");
    return v;
}

extern "C" __global__ void __launch_bounds__(256, 5)
k_fused(const float* __restrict__ Q, const float* __restrict__ K,
        const float* __restrict__ V, float* __restrict__ O)
{
    __shared__ float4 c_s[CHUNK][16];      // 16 KB: group-local cumsum
    __shared__ float  gs[NGRP][68];        // group sums (transpose buf)
    __shared__ float  offs[NGRP][68];      // per-group total offsets
    __shared__ float4 basev[16];           // chunk base prefix
    __shared__ float  pre[4][DIM];         // lookback partials
    __shared__ float  r_row[CHUNK];        // per-row gate denominators

    const int blk = blockIdx.x;
    const int ch  = blk >> 6;              // chunk-major launch order
    const int bh  = blk & 63;
    const int fbase = bh * NCHUNK;
    const size_t cbase = ((size_t)bh * SEQ + (size_t)ch * CHUNK) * DIM;
    const int tid  = threadIdx.x;
    const int lane = tid & 31;
    const int w    = tid >> 5;

    // ---------- r_row at kernel entry: Q/K streamed & reduced immediately ----------
    {
        const int row  = tid >> 2;         // 0..63
        const int part = tid & 3;          // quarter-row (16 floats = 64B)
        const float* qp = Q + cbase + (size_t)row * DIM + part * 16;
        const float* kp = K + cbase + (size_t)row * DIM + part * 16;
        float4 q0 = __ldcs((const float4*)(qp));
        float4 q1 = __ldcs((const float4*)(qp + 4));
        float4 q2 = __ldcs((const float4*)(qp + 8));
        float4 q3 = __ldcs((const float4*)(qp + 12));
        float4 k0 = __ldcs((const float4*)(kp));
        float4 k1 = __ldcs((const float4*)(kp + 4));
        float4 k2 = __ldcs((const float4*)(kp + 8));
        float4 k3 = __ldcs((const float4*)(kp + 12));
        float sq = dot4(q0) + dot4(q1) + dot4(q2) + dot4(q3);
        float sk = dot4(k0) + dot4(k1) + dot4(k2) + dot4(k3);
        sq += __shfl_xor_sync(0xFFFFFFFFu, sq, 1);
        sq += __shfl_xor_sync(0xFFFFFFFFu, sq, 2);
        sk += __shfl_xor_sync(0xFFFFFFFFu, sk, 1);
        sk += __shfl_xor_sync(0xFFFFFFFFu, sk, 2);
        if (part == 0)
            r_row[row] = sqrtf(sq) + sqrtf(sk) + 1.0f + 2e-8f;
    }

    // ---------------- Phase A: per-group cumsum (4 rows/thread) ----------------
    {
        const int q = tid & 15;            // d-quad
        const int g = tid >> 4;            // group 0..15 (4 rows each)
        const float* vp = V + cbase + (size_t)(g * 4) * DIM + q * 4;
        float4 v0 = *(const float4*)(vp);
        float4 v1 = *(const float4*)(vp + DIM);
        float4 v2 = *(const float4*)(vp + 2 * DIM);
        float4 v3 = *(const float4*)(vp + 3 * DIM);

        float4 a0 = sw4(v0);
        float4 a1 = add4(a0, sw4(v1));
        float4 a2 = add4(a1, sw4(v2));
        float4 a3 = add4(a2, sw4(v3));
        c_s[g * 4 + 0][q] = a0;
        c_s[g * 4 + 1][q] = a1;
        c_s[g * 4 + 2][q] = a2;
        c_s[g * 4 + 3][q] = a3;
        *(float4*)&gs[g][q * 4] = a3;
    }
    __syncthreads();                       // orders c_s, gs AND r_row

    // ---------------- Warp-shuffle scan over 16 group sums ----------------
    const int seg = lane >> 4;
    const int sl  = lane & 15;
    const int qq  = w * 2 + seg;

    {
        float4 incl = *(const float4*)&gs[sl][qq * 4];
        #pragma unroll
        for (int st = 1; st < 16; st <<= 1) {
            float4 t;
            t.x = __shfl_up_sync(0xFFFFFFFFu, incl.x, st);
            t.y = __shfl_up_sync(0xFFFFFFFFu, incl.y, st);
            t.z = __shfl_up_sync(0xFFFFFFFFu, incl.z, st);
            t.w = __shfl_up_sync(0xFFFFFFFFu, incl.w, st);
            if (sl >= st) incl = add4(incl, t);
        }
        if (sl == 15) {                    // publish chunk aggregate
            *(float4*)(g_agg + ((size_t)fbase + ch) * DIM + qq * 4) = incl;
            __threadfence();
        }
        float4 excl;
        excl.x = __shfl_up_sync(0xFFFFFFFFu, incl.x, 1);
        excl.y = __shfl_up_sync(0xFFFFFFFFu, incl.y, 1);
        excl.z = __shfl_up_sync(0xFFFFFFFFu, incl.z, 1);
        excl.w = __shfl_up_sync(0xFFFFFFFFu, incl.w, 1);
        if (sl == 0) excl = make_float4(0.f, 0.f, 0.f, 0.f);
        *(float4*)&offs[sl][qq * 4] = excl;
    }
    __syncthreads();
    if (tid == 0) atomicExch(&g_flag[fbase + ch], 1);

    // ---------------- Lookback ----------------
    if (ch > 0) {
        if (tid < ch) {
            const int* fp = g_flag + fbase + tid;
            while (ld_acq(fp) == 0) __nanosleep(32);
        }
        __syncthreads();
        {
            const int d = tid & 63, j = tid >> 6;
            float p = 0.f;
            for (int cc = j; cc < ch; cc += 4)
                p += __ldcg(g_agg + ((size_t)(fbase + cc)) * DIM + d);
            pre[j][d] = p;
        }
        __syncthreads();
        if (tid < 16) {
            float4 b;
            b.x = pre[0][tid*4+0] + pre[1][tid*4+0] + pre[2][tid*4+0] + pre[3][tid*4+0];
            b.y = pre[0][tid*4+1] + pre[1][tid*4+1] + pre[2][tid*4+1] + pre[3][tid*4+1];
            b.z = pre[0][tid*4+2] + pre[1][tid*4+2] + pre[2][tid*4+2] + pre[3][tid*4+2];
            b.w = pre[0][tid*4+3] + pre[1][tid*4+3] + pre[2][tid*4+3] + pre[3][tid*4+3];
            basev[tid] = b;
        }
    } else {
        if (tid < 16) basev[tid] = make_float4(0.f, 0.f, 0.f, 0.f);
    }
    __syncthreads();

    // Per-group total offset = chunk base + exclusive group prefix
    {
        float4 o = add4(*(const float4*)&offs[sl][qq * 4], basev[qq]);
        *(float4*)&offs[sl][qq * 4] = o;
    }
    __syncthreads();

    // ---------------- Phase B: no global loads; 8-lane butterflies ----------------
    const int rid = lane >> 3;        // row slot 0..3
    const int l8  = lane & 7;         // channels 8*l8 .. 8*l8+7

    #pragma unroll
    for (int it = 0; it < 2; it++) {
        const int s   = w * 8 + it * 4 + rid;   // row within chunk
        const int grp = s >> 2;
        const size_t roff = cbase + (size_t)s * DIM + l8 * 8;

        float4 va = *(const float4*)(V + roff);        // L1 hit
        float4 vb = *(const float4*)(V + roff + 4);
        float4 ca = add4(c_s[s][l8 * 2 + 0], *(const float4*)&offs[grp][l8 * 8 + 0]);
        float4 cb = add4(c_s[s][l8 * 2 + 1], *(const float4*)&offs[grp][l8 * 8 + 4]);

        float sc = dot4(ca) + dot4(cb);
        #pragma unroll
        for (int m = 4; m; m >>= 1)
            sc += __shfl_xor_sync(0xFFFFFFFFu, sc, m);

        float rms_c = rsqrtf(sc * (1.0f / DIM) + 1e-5f);
        float scale = __fdividef(rms_c, r_row[s]);     // LDS broadcast

        float m0 = ca.x * scale, m1 = ca.y * scale;
        float m2 = ca.z * scale, m3 = ca.w * scale;
        float m4 = cb.x * scale, m5 = cb.y * scale;
        float m6 = cb.z * scale, m7 = cb.w * scale;
        float o0 = va.x * (1.0f + m0 * sigf(m0));
        float o1 = va.y * (1.0f + m1 * sigf(m1));
        float o2 = va.z * (1.0f + m2 * sigf(m2));
        float o3 = va.w * (1.0f + m3 * sigf(m3));
        float o4 = vb.x * (1.0f + m4 * sigf(m4));
        float o5 = vb.y * (1.0f + m5 * sigf(m5));
        float o6 = vb.z * (1.0f + m6 * sigf(m6));
        float o7 = vb.w * (1.0f + m7 * sigf(m7));

        float so = o0*o0 + o1*o1 + o2*o2 + o3*o3 + o4*o4 + o5*o5 + o6*o6 + o7*o7;
        #pragma unroll
        for (int m = 4; m; m >>= 1)
            so += __shfl_xor_sync(0xFFFFFFFFu, so, m);

        float rms_o = rsqrtf(so * (1.0f / DIM) + 1e-5f);
        float4 oa = make_float4(o0 * rms_o, o1 * rms_o, o2 * rms_o, o3 * rms_o);
        float4 ob = make_float4(o4 * rms_o, o5 * rms_o, o6 * rms_o, o7 * rms_o);
        __stcs((float4*)(O + roff), oa);
        __stcs((float4*)(O + roff + 4), ob);
    }
}

// ---------------------------------------------------------------------------
extern "C" void kernel_launch(void* const* d_in, const int* in_sizes, int n_in,
                              void* d_out, int out_size) {
    const float* Q = (const float*)d_in[0];
    const float* K = (const float*)d_in[1];
    const float* V = (const float*)d_in[2];
    float* O = (float*)d_out;

    void* fp = nullptr;
    cudaGetSymbolAddress(&fp, g_flag);
    cudaMemsetAsync(fp, 0, NBLK * sizeof(int), 0);

    k_fused<<<NBLK, 256>>>(Q, K, V, O);
}

// round 17
// speedup vs baseline: 1.1870x; 1.1870x over previous
#include <cuda_runtime.h>
#include <cstdint>
#include <math.h>

// Q,K,V,O : [4,16,4096,64] fp32.
// out = rmsnorm( V * (1 + silu( rmsnorm(cumsum_s(silu(V)*V)) / (||Q||+||K||+1+2e-8) )) )
//
// R9 champion kernel (decoupled-lookback scan, chunk-major order, 8-lane
// phase-B butterflies, Q/K loaded inside phase B) + epoch-coded flags:
// flags are never reset, so the cudaMemsetAsync graph node is eliminated.
// epoch = atomicAdd(g_counter)/NBLK + 1 is launch-unique and identical for
// all CTAs of one launch; pollers wait for flag == epoch.

#define BH      64
#define SEQ     4096
#define DIM     64
#define CHUNK   64
#define NCHUNK  64
#define NGRP    16
#define NBLK    (BH * NCHUNK)   // 4096

__device__ float        g_agg[NBLK * DIM];   // [bh][ch][d] (fully rewritten each launch)
__device__ unsigned int g_flag[NBLK];        // epoch stamps (never reset)
__device__ unsigned int g_counter;           // monotonic launch counter

__device__ __forceinline__ float sigf(float x) {
    return __fdividef(1.0f, 1.0f + __expf(-x));
}
__device__ __forceinline__ float4 add4(float4 a, float4 b) {
    return make_float4(a.x + b.x, a.y + b.y, a.z + b.z, a.w + b.w);
}
__device__ __forceinline__ float4 sw4(float4 v) {
    return make_float4(v.x * v.x * sigf(v.x), v.y * v.y * sigf(v.y),
                       v.z * v.z * sigf(v.z), v.w * v.w * sigf(v.w));
}
__device__ __forceinline__ float dot4(float4 a) {
    return a.x * a.x + a.y * a.y + a.z * a.z + a.w * a.w;
}
__device__ __forceinline__ unsigned int ld_acq_u(const unsigned int* p) {
    unsigned int v;
    asm volatile("ld.global.acquire.gpu.b32 %0, [%1];" : "=r"(v) : "l"(p) : "memory");
    return v;
}

extern "C" __global__ void __launch_bounds__(256, 5)
k_fused(const float* __restrict__ Q, const float* __restrict__ K,
        const float* __restrict__ V, float* __restrict__ O)
{
    __shared__ float4 c_s[CHUNK][16];      // 16 KB: group-local cumsum
    __shared__ float  gs[NGRP][68];        // group sums (transpose buf)
    __shared__ float  offs[NGRP][68];      // per-group total offsets
    __shared__ float4 basev[16];           // chunk base prefix
    __shared__ float  pre[4][DIM];         // lookback partials
    __shared__ unsigned int s_epoch;       // launch epoch

    const int blk = blockIdx.x;
    const int ch  = blk >> 6;              // chunk-major launch order
    const int bh  = blk & 63;
    const int fbase = bh * NCHUNK;
    const size_t cbase = ((size_t)bh * SEQ + (size_t)ch * CHUNK) * DIM;
    const int tid  = threadIdx.x;
    const int lane = tid & 31;
    const int w    = tid >> 5;

    // ---------- Launch epoch (hidden under phase-A load latency) ----------
    if (tid == 0)
        s_epoch = atomicAdd(&g_counter, 1u) / (unsigned int)NBLK + 1u;

    // ---------------- Phase A: per-group cumsum (4 rows/thread) ----------------
    {
        const int q = tid & 15;            // d-quad
        const int g = tid >> 4;            // group 0..15 (4 rows each)
        const float* vp = V + cbase + (size_t)(g * 4) * DIM + q * 4;
        float4 v0 = *(const float4*)(vp);
        float4 v1 = *(const float4*)(vp + DIM);
        float4 v2 = *(const float4*)(vp + 2 * DIM);
        float4 v3 = *(const float4*)(vp + 3 * DIM);

        float4 a0 = sw4(v0);
        float4 a1 = add4(a0, sw4(v1));
        float4 a2 = add4(a1, sw4(v2));
        float4 a3 = add4(a2, sw4(v3));
        c_s[g * 4 + 0][q] = a0;
        c_s[g * 4 + 1][q] = a1;
        c_s[g * 4 + 2][q] = a2;
        c_s[g * 4 + 3][q] = a3;
        *(float4*)&gs[g][q * 4] = a3;
    }
    __syncthreads();                       // orders c_s, gs AND s_epoch

    const unsigned int epoch = s_epoch;

    // ---------------- Warp-shuffle scan over 16 group sums ----------------
    const int seg = lane >> 4;
    const int sl  = lane & 15;
    const int qq  = w * 2 + seg;

    {
        float4 incl = *(const float4*)&gs[sl][qq * 4];
        #pragma unroll
        for (int st = 1; st < 16; st <<= 1) {
            float4 t;
            t.x = __shfl_up_sync(0xFFFFFFFFu, incl.x, st);
            t.y = __shfl_up_sync(0xFFFFFFFFu, incl.y, st);
            t.z = __shfl_up_sync(0xFFFFFFFFu, incl.z, st);
            t.w = __shfl_up_sync(0xFFFFFFFFu, incl.w, st);
            if (sl >= st) incl = add4(incl, t);
        }
        if (sl == 15) {                    // publish chunk aggregate
            *(float4*)(g_agg + ((size_t)fbase + ch) * DIM + qq * 4) = incl;
            __threadfence();
        }
        float4 excl;
        excl.x = __shfl_up_sync(0xFFFFFFFFu, incl.x, 1);
        excl.y = __shfl_up_sync(0xFFFFFFFFu, incl.y, 1);
        excl.z = __shfl_up_sync(0xFFFFFFFFu, incl.z, 1);
        excl.w = __shfl_up_sync(0xFFFFFFFFu, incl.w, 1);
        if (sl == 0) excl = make_float4(0.f, 0.f, 0.f, 0.f);
        *(float4*)&offs[sl][qq * 4] = excl;
    }
    __syncthreads();
    if (tid == 0) atomicExch(&g_flag[fbase + ch], epoch);

    // ---------------- Lookback ----------------
    if (ch > 0) {
        if (tid < ch) {
            const unsigned int* fp = g_flag + fbase + tid;
            while (ld_acq_u(fp) != epoch) __nanosleep(32);
        }
        __syncthreads();
        {
            const int d = tid & 63, j = tid >> 6;
            float p = 0.f;
            for (int cc = j; cc < ch; cc += 4)
                p += __ldcg(g_agg + ((size_t)(fbase + cc)) * DIM + d);
            pre[j][d] = p;
        }
        __syncthreads();
        if (tid < 16) {
            float4 b;
            b.x = pre[0][tid*4+0] + pre[1][tid*4+0] + pre[2][tid*4+0] + pre[3][tid*4+0];
            b.y = pre[0][tid*4+1] + pre[1][tid*4+1] + pre[2][tid*4+1] + pre[3][tid*4+1];
            b.z = pre[0][tid*4+2] + pre[1][tid*4+2] + pre[2][tid*4+2] + pre[3][tid*4+2];
            b.w = pre[0][tid*4+3] + pre[1][tid*4+3] + pre[2][tid*4+3] + pre[3][tid*4+3];
            basev[tid] = b;
        }
    } else {
        if (tid < 16) basev[tid] = make_float4(0.f, 0.f, 0.f, 0.f);
    }
    __syncthreads();

    // Per-group total offset = chunk base + exclusive group prefix
    {
        float4 o = add4(*(const float4*)&offs[sl][qq * 4], basev[qq]);
        *(float4*)&offs[sl][qq * 4] = o;
    }
    __syncthreads();

    // ---------------- Phase B: 8-lane rows, 4 rows/warp-iteration ----------------
    const int rid = lane >> 3;        // row slot 0..3
    const int l8  = lane & 7;         // channels 8*l8 .. 8*l8+7

    #pragma unroll
    for (int it = 0; it < 2; it++) {
        const int s   = w * 8 + it * 4 + rid;   // row within chunk
        const int grp = s >> 2;
        const size_t roff = cbase + (size_t)s * DIM + l8 * 8;

        float4 qa = __ldcs((const float4*)(Q + roff));
        float4 qb = __ldcs((const float4*)(Q + roff + 4));
        float4 ka = __ldcs((const float4*)(K + roff));
        float4 kb = __ldcs((const float4*)(K + roff + 4));
        float4 va = *(const float4*)(V + roff);        // L1 hit
        float4 vb = *(const float4*)(V + roff + 4);
        float4 ca = add4(c_s[s][l8 * 2 + 0], *(const float4*)&offs[grp][l8 * 8 + 0]);
        float4 cb = add4(c_s[s][l8 * 2 + 1], *(const float4*)&offs[grp][l8 * 8 + 4]);

        float sq = dot4(qa) + dot4(qb);
        float sk = dot4(ka) + dot4(kb);
        float sc = dot4(ca) + dot4(cb);
        #pragma unroll
        for (int m = 4; m; m >>= 1) {              // 8-lane butterfly
            sq += __shfl_xor_sync(0xFFFFFFFFu, sq, m);
            sk += __shfl_xor_sync(0xFFFFFFFFu, sk, m);
            sc += __shfl_xor_sync(0xFFFFFFFFu, sc, m);
        }

        float rms_c = rsqrtf(sc * (1.0f / DIM) + 1e-5f);
        float r     = sqrtf(sq) + sqrtf(sk) + 1.0f + 2e-8f;
        float scale = __fdividef(rms_c, r);

        float m0 = ca.x * scale, m1 = ca.y * scale;
        float m2 = ca.z * scale, m3 = ca.w * scale;
        float m4 = cb.x * scale, m5 = cb.y * scale;
        float m6 = cb.z * scale, m7 = cb.w * scale;
        float o0 = va.x * (1.0f + m0 * sigf(m0));
        float o1 = va.y * (1.0f + m1 * sigf(m1));
        float o2 = va.z * (1.0f + m2 * sigf(m2));
        float o3 = va.w * (1.0f + m3 * sigf(m3));
        float o4 = vb.x * (1.0f + m4 * sigf(m4));
        float o5 = vb.y * (1.0f + m5 * sigf(m5));
        float o6 = vb.z * (1.0f + m6 * sigf(m6));
        float o7 = vb.w * (1.0f + m7 * sigf(m7));

        float so = o0*o0 + o1*o1 + o2*o2 + o3*o3 + o4*o4 + o5*o5 + o6*o6 + o7*o7;
        #pragma unroll
        for (int m = 4; m; m >>= 1)
            so += __shfl_xor_sync(0xFFFFFFFFu, so, m);

        float rms_o = rsqrtf(so * (1.0f / DIM) + 1e-5f);
        float4 oa = make_float4(o0 * rms_o, o1 * rms_o, o2 * rms_o, o3 * rms_o);
        float4 ob = make_float4(o4 * rms_o, o5 * rms_o, o6 * rms_o, o7 * rms_o);
        __stcs((float4*)(O + roff), oa);
        __stcs((float4*)(O + roff + 4), ob);
    }
}

// ---------------------------------------------------------------------------
extern "C" void kernel_launch(void* const* d_in, const int* in_sizes, int n_in,
                              void* d_out, int out_size) {
    const float* Q = (const float*)d_in[0];
    const float* K = (const float*)d_in[1];
    const float* V = (const float*)d_in[2];
    float* O = (float*)d_out;

    k_fused<<<NBLK, 256>>>(Q, K, V, O);   // single graph node; no memset needed
}